// round 17
// baseline (speedup 1.0000x reference)
#include <cuda_runtime.h>
#include <cuda_fp16.h>
#include <cstdint>

#define HIN 512
#define WIN 512
#define NP  724
#define NA  180
#define CENTER 361.5f
#define PI_D 3.14159265358979323846
#define TILE 32
#define NT   23              // ceil(724/32)
#define QSTR 528             // quad row stride (8 B quads: 528*8 = 4224 B = 33 lines)
#define QROWS 514

// fp16 quad buffers: buf[(j+2)*QSTR + (i+2)] = (half2(A,C), half2(B,D)) for cell (j,i):
//   A=a(j,i)  C=a(j+1,i)  B=a(j,i+1)  D=a(j+1,i+1)
//   g_qN: a(j,i) = img[j][i]   (shallow: i = image col, j = image row)
//   g_qT: a(j,i) = img[i][j]   (steep:   i = image row, j = image col)
__device__ uint2 g_qN[QROWS * QSTR];
__device__ uint2 g_qT[QROWS * QSTR];

static __device__ __forceinline__ uint2 pack_quad(float A, float C, float B, float D) {
    __half2 ac = __floats2half2_rn(A, C);
    __half2 bd = __floats2half2_rn(B, D);
    uint2 q;
    q.x = *reinterpret_cast<unsigned*>(&ac);
    q.y = *reinterpret_cast<unsigned*>(&bd);
    return q;
}

__global__ __launch_bounds__(256) void prep_kernel(const float* __restrict__ img,
                                                   float* __restrict__ sino) {
    // fused sinogram zeroing: 256 blocks x 256 threads x 2 covers 130320
    const int gid = ((blockIdx.y * 16 + blockIdx.x) * 256 + threadIdx.x) * 2;
    if (gid < NA * NP)     sino[gid] = 0.f;
    if (gid + 1 < NA * NP) sino[gid + 1] = 0.f;

    __shared__ float tile[34][36];
    const int bx = blockIdx.x * 32;
    const int by = blockIdx.y * 32;
    for (int idx = threadIdx.x; idx < 34 * 34; idx += 256) {
        const int r = idx / 34, c = idx % 34;
        const int gy = by - 1 + r, gx = bx - 1 + c;
        float v = 0.f;
        if ((unsigned)gy < (unsigned)HIN && (unsigned)gx < (unsigned)WIN)
            v = img[gy * WIN + gx];
        tile[r][c] = v;
    }
    __syncthreads();
    for (int idx = threadIdx.x; idx < 33 * 33; idx += 256) {
        const int r = idx / 33, c = idx % 33;
        g_qN[(size_t)(by + 1 + r) * QSTR + (bx + 1 + c)] =
            pack_quad(tile[r][c], tile[r + 1][c], tile[r][c + 1], tile[r + 1][c + 1]);
    }
    for (int idx = threadIdx.x; idx < 33 * 33; idx += 256) {
        const int c = idx / 33, r = idx % 33;
        g_qT[(size_t)(bx + 1 + c) * QSTR + (by + 1 + r)] =
            pack_quad(tile[r][c], tile[r][c + 1], tile[r + 1][c], tile[r + 1][c + 1]);
    }
}

static __device__ __forceinline__ float lerp_quad(uint2 qi, float wi, float wj) {
    const float2 f0 = __half22float2(*reinterpret_cast<__half2*>(&qi.x));  // (A, C)
    const float2 f1 = __half22float2(*reinterpret_cast<__half2*>(&qi.y));  // (B, D)
    const float top = fmaf(wi, f1.x - f0.x, f0.x);
    const float bot = fmaf(wi, f1.y - f0.y, f0.y);
    return fmaf(wj, bot - top, top);
}

// Block = 32x32 output tile of one angle; warp footprint 8x x 4y.
// Block-uniform specialization: fully-OOB -> zero-store fast exit;
// fully-interior -> unconditional LDG.64; boundary -> predicated LDG.64.
template <bool STEEP>
__global__ __launch_bounds__(256) void radon_kernel(
    float* __restrict__ sino,        // [180,724]  (pre-zeroed, atomicAdd)
    float* __restrict__ rot)         // [180,724,724]
{
    __shared__ __align__(16) float sm[32 * 40];

    const int X0 = blockIdx.x * TILE;
    const int Y0 = blockIdx.y * TILE;
    const int n  = STEEP ? (int)blockIdx.z + 45
                         : ((int)blockIdx.z < 45 ? (int)blockIdx.z : (int)blockIdx.z + 90);
    const int t   = threadIdx.x;
    const int lx  = t & 7;           // 0..7  (output-x lane)
    const int row = t >> 3;          // 0..31 (output-y within tile)

    float s, c;
    sincosf((float)n * (float)(PI_D / 179.0), &s, &c);

    // tile bbox in buffer space (linear map -> corners suffice)
    const float B0 = CENTER - 104.0f;    // folds -PAD+2
    const float u0 = (float)X0 - CENTER, u1 = u0 + 31.0f;
    const float v0 = (float)Y0 - CENTER, v1 = v0 + 31.0f;
    const float e00x = c * u0 - s * v0, e10x = c * u1 - s * v0;
    const float e01x = c * u0 - s * v1, e11x = c * u1 - s * v1;
    const float e00y = s * u0 + c * v0, e10y = s * u1 + c * v0;
    const float e01y = s * u0 + c * v1, e11y = s * u1 + c * v1;
    const float ixmin = B0 + fminf(fminf(e00x, e10x), fminf(e01x, e11x));
    const float ixmax = B0 + fmaxf(fmaxf(e00x, e10x), fmaxf(e01x, e11x));
    const float iymin = B0 + fminf(fminf(e00y, e10y), fminf(e01y, e11y));
    const float iymax = B0 + fmaxf(fmaxf(e00y, e10y), fmaxf(e01y, e11y));
    const int cimin = (int)floorf(STEEP ? iymin : ixmin);
    const int cimax = (int)floorf(STEEP ? iymax : ixmax);
    const int rjmin = (int)floorf(STEEP ? ixmin : iymin);
    const int rjmax = (int)floorf(STEEP ? ixmax : iymax);

    const bool active = (cimax >= 1) && (cimin <= 513) &&
                        (rjmax >= 1) && (rjmin <= 513);

    const int row_r = t >> 3;
    const int c4    = (t & 7) << 2;
    const int ygs   = Y0 + row_r;

    if (!active) {
        if (ygs < NP && X0 + c4 < NP)
            *reinterpret_cast<float4*>(&rot[((size_t)n * NP + ygs) * NP + X0 + c4]) =
                make_float4(0.f, 0.f, 0.f, 0.f);
        return;
    }

    const bool allin = (cimin >= 1) && (cimax <= 513) &&
                       (rjmin >= 1) && (rjmax <= 513);

    const float v  = (float)(Y0 + row) - CENTER;
    const float uu = (float)(X0 + lx) - CENTER;
    float ixb = fmaf(c, uu, fmaf(-s, v, B0));
    float iyb = fmaf(s, uu, fmaf( c, v, B0));
    const float dix = 8.0f * c;
    const float diy = 8.0f * s;

    const uint2* __restrict__ buf = STEEP ? g_qT : g_qN;
    const int xg0 = X0 + lx;
    float sum = 0.0f;

    if (allin) {
#pragma unroll
        for (int k = 0; k < 4; k++) {
            const float fx = floorf(ixb);
            const float fy = floorf(iyb);
            const float wx = ixb - fx;
            const float wy = iyb - fy;
            const int   ci = (int)(STEEP ? fy : fx);
            const int   rj = (int)(STEEP ? fx : fy);
            const float wi = STEEP ? wy : wx;
            const float wj = STEEP ? wx : wy;

            const uint2 qi = __ldg(buf + rj * QSTR + ci);
            const float r  = lerp_quad(qi, wi, wj);

            sm[row * 40 + lx + 8 * k] = r;
            if (xg0 + 8 * k < NP) sum += r;
            ixb += dix;
            iyb += diy;
        }
    } else {
#pragma unroll
        for (int k = 0; k < 4; k++) {
            const float fx = floorf(ixb);
            const float fy = floorf(iyb);
            const float wx = ixb - fx;
            const float wy = iyb - fy;
            const int   ci = (int)(STEEP ? fy : fx);
            const int   rj = (int)(STEEP ? fx : fy);
            const float wi = STEEP ? wy : wx;
            const float wj = STEEP ? wx : wy;

            const unsigned inside =
                ((unsigned)(ci - 1) < 513u) & ((unsigned)(rj - 1) < 513u);
            uint2 qi = make_uint2(0u, 0u);
            const uint2* p = buf + (size_t)rj * QSTR + ci;
            asm volatile(
                "{\n\t"
                ".reg .pred p0;\n\t"
                "setp.ne.u32 p0, %2, 0;\n\t"
                "@p0 ld.global.nc.v2.b32 {%0, %1}, [%3];\n\t"
                "}"
                : "+r"(qi.x), "+r"(qi.y)
                : "r"(inside), "l"(p));
            const float r = lerp_quad(qi, wi, wj);

            sm[row * 40 + lx + 8 * k] = r;
            if (xg0 + 8 * k < NP) sum += r;
            ixb += dix;
            iyb += diy;
        }
    }

    // sinogram: reduce over the 8 lx lanes (consecutive lanes share a row)
#pragma unroll
    for (int o = 4; o > 0; o >>= 1)
        sum += __shfl_down_sync(0xffffffffu, sum, o);
    const int yg = Y0 + row;
    if (lx == 0 && yg < NP)
        atomicAdd(&sino[(size_t)n * NP + yg], sum);

    __syncthreads();

    // transposed store: STG.128, one line per 8 lanes
    if (ygs < NP && X0 + c4 < NP) {
        const float4 val = *reinterpret_cast<const float4*>(&sm[row_r * 40 + c4]);
        *reinterpret_cast<float4*>(&rot[((size_t)n * NP + ygs) * NP + X0 + c4]) = val;
    }
}

extern "C" void kernel_launch(void* const* d_in, const int* in_sizes, int n_in,
                              void* d_out, int out_size) {
    const float* x = (const float*)d_in[0];
    float* sino = (float*)d_out;                 // [180,724]
    float* rot  = sino + (size_t)NA * NP;        // [180,1,724,724]

    prep_kernel<<<dim3(16, 16), 256>>>(x, sino);
    dim3 grid(NT, NT, 90);
    radon_kernel<false><<<grid, 256>>>(sino, rot);
    radon_kernel<true ><<<grid, 256>>>(sino, rot);
}